// round 6
// baseline (speedup 1.0000x reference)
#include <cuda_runtime.h>
#include <math.h>

#define T_SEQ   1024
#define BATCH   256
#define IN_DIM  64
#define HID     512
#define NCLS    10
#define KTOT    (HID + IN_DIM)      // 576
#define GROUPS  16                  // batch groups
#define CPG     8                   // CTAs per group (j-split)
#define RPG     16                  // batch rows per group
#define JSL     64                  // j columns per CTA
#define NTHR    256
#define NSLC    32                  // k-slices = full warp
#define KE      (KTOT / NSLC)       // 18 k per lane
#define KP      (KE / 2)            // 9 packed k-pairs per lane
#define JPW     8                   // j columns per warp (= per thread)

__device__ float             g_hbuf[2][BATCH * HID];
__device__ unsigned          g_cnt[GROUPS];
__device__ volatile unsigned g_sense[GROUPS];

__device__ __forceinline__ void ffma2(unsigned long long& d,
                                      unsigned long long a,
                                      unsigned long long b) {
    asm("fma.rn.f32x2 %0, %1, %2, %0;" : "+l"(d) : "l"(a), "l"(b));
}
__device__ __forceinline__ float2 unpack2(unsigned long long a) {
    float2 r;
    asm("mov.b64 {%0,%1}, %2;" : "=f"(r.x), "=f"(r.y) : "l"(a));
    return r;
}
__device__ __forceinline__ unsigned long long pack2(float x, float y) {
    unsigned long long d;
    asm("mov.b64 %0, {%1,%2};" : "=l"(d) : "f"(x), "f"(y));
    return d;
}

__global__ __launch_bounds__(NTHR, 1)
void rnn_regw2(const float* __restrict__ x,   const float* __restrict__ Whx,
               const float* __restrict__ Whh, const float* __restrict__ Wph,
               const float* __restrict__ bh,  const float* __restrict__ bp,
               float* __restrict__ out)
{
    extern __shared__ float hs[];           // RPG x KTOT plain h||x staging

    const int tid  = threadIdx.x;
    const int lane = tid & 31;              // k-slice 0..31
    const int wrp  = tid >> 5;              // warp 0..7 -> j-octet
    const int g    = blockIdx.x / CPG;      // batch group
    const int jc   = blockIdx.x % CPG;      // j-slice index of CTA
    const int jb   = jc * JSL;
    const int j0w  = jb + wrp * JPW;        // this warp's 8 j columns
    const int row0 = g * RPG;

    // ---- one-time: weights into registers, packed over k-pairs ----
    // wreg[kp][jj] = (W[k][j0w+jj], W[k+1][j0w+jj]),  k = lane*KE + 2*kp
    unsigned long long wreg[KP][JPW];
    #pragma unroll
    for (int kp = 0; kp < KP; ++kp) {
        const int k = lane * KE + 2 * kp;
        #pragma unroll
        for (int jj = 0; jj < JPW; ++jj) {
            float wa = (k     < HID) ? __ldg(Whh + k * HID + j0w + jj)
                                     : __ldg(Whx + (k - HID) * HID + j0w + jj);
            float wb = (k + 1 < HID) ? __ldg(Whh + (k + 1) * HID + j0w + jj)
                                     : __ldg(Whx + (k + 1 - HID) * HID + j0w + jj);
            wreg[kp][jj] = pack2(wa, wb);
        }
    }

    // After reduction, lane l (l<16) holds output o = 8*b0 + 4*b1 + 2*b2 + b3
    const int my_row = lane & 1;                                    // o >> 3
    const int my_col = ((lane >> 1) & 1) * 4 + ((lane >> 2) & 1) * 2
                     + ((lane >> 3) & 1);                           // o & 7
    const float my_bias = __ldg(bh + j0w + my_col);

    unsigned local_sense = 0;

    for (int t = 0; t < T_SEQ; ++t) {
        const int br = t & 1, bw = br ^ 1;

        // ---- stage h (plain) into SMEM ----
        if (t == 0) {
            const float4 z = make_float4(0.f, 0.f, 0.f, 0.f);
            #pragma unroll
            for (int u = 0; u < 8; ++u) {
                int i = tid + u * NTHR;                 // 0..2047
                int r = i >> 7, c = i & 127;            // 128 float4 of h per row
                ((float4*)(hs + r * KTOT))[c] = z;
            }
        } else {
            const float4* src = (const float4*)g_hbuf[br];
            #pragma unroll
            for (int u = 0; u < 8; ++u) {
                int i = tid + u * NTHR;
                int r = i >> 7, c = i & 127;
                ((float4*)(hs + r * KTOT))[c] =
                    __ldcg(src + (row0 + r) * (HID / 4) + c);
            }
        }
        // ---- stage x_t into SMEM tail ----
        {
            int r = tid >> 4, q = tid & 15;             // 16 float4 per row
            const float4* xp = (const float4*)(x + (size_t)(row0 + r) * (T_SEQ * IN_DIM)
                                                 + (size_t)t * IN_DIM);
            ((float4*)(hs + r * KTOT + HID))[q] = __ldg(xp + q);
        }
        __syncthreads();

        // ---- 8 passes of 2 rows ----
        #pragma unroll 1
        for (int p = 0; p < 8; ++p) {
            unsigned long long acc[2][JPW];
            #pragma unroll
            for (int rr = 0; rr < 2; ++rr)
                #pragma unroll
                for (int jj = 0; jj < JPW; ++jj) acc[rr][jj] = 0ull;

            #pragma unroll
            for (int rr = 0; rr < 2; ++rr) {
                const unsigned long long* hp =
                    (const unsigned long long*)(hs + (p * 2 + rr) * KTOT + lane * KE);
                #pragma unroll
                for (int i = 0; i < KP; ++i) {          // 9 LDS.64, 72 FFMA2
                    unsigned long long hv = hp[i];
                    #pragma unroll
                    for (int jj = 0; jj < JPW; ++jj)
                        ffma2(acc[rr][jj], hv, wreg[i][jj]);
                }
            }

            // collapse the packed k-pair
            float v[16];
            #pragma unroll
            for (int rr = 0; rr < 2; ++rr)
                #pragma unroll
                for (int jj = 0; jj < JPW; ++jj) {
                    float2 u = unpack2(acc[rr][jj]);
                    v[rr * 8 + jj] = u.x + u.y;
                }

            // recursive-halving butterfly over 32 lanes (16 outputs)
            float s8[8];
            #pragma unroll
            for (int i = 0; i < 8; ++i) {
                float keep = (lane & 1) ? v[i + 8] : v[i];
                float send = (lane & 1) ? v[i]     : v[i + 8];
                s8[i] = keep + __shfl_xor_sync(0xffffffffu, send, 1, 32);
            }
            float s4[4];
            #pragma unroll
            for (int i = 0; i < 4; ++i) {
                float keep = (lane & 2) ? s8[i + 4] : s8[i];
                float send = (lane & 2) ? s8[i]     : s8[i + 4];
                s4[i] = keep + __shfl_xor_sync(0xffffffffu, send, 2, 32);
            }
            float s2[2];
            #pragma unroll
            for (int i = 0; i < 2; ++i) {
                float keep = (lane & 4) ? s4[i + 2] : s4[i];
                float send = (lane & 4) ? s4[i]     : s4[i + 2];
                s2[i] = keep + __shfl_xor_sync(0xffffffffu, send, 4, 32);
            }
            float s1;
            {
                float keep = (lane & 8) ? s2[1] : s2[0];
                float send = (lane & 8) ? s2[0] : s2[1];
                s1 = keep + __shfl_xor_sync(0xffffffffu, send, 8, 32);
            }
            s1 += __shfl_xor_sync(0xffffffffu, s1, 16, 32);

            if (lane < 16) {
                float o = tanhf(s1 + my_bias);
                __stcg(g_hbuf[bw] + (size_t)(row0 + p * 2 + my_row) * HID
                                  + j0w + my_col, o);
            }
        }

        // ---- per-group barrier (8 CTAs), sense-reversing ----
        __syncthreads();
        if (tid == 0) {
            __threadfence();
            unsigned ls = local_sense ^ 1;
            if (atomicAdd(&g_cnt[g], 1u) == CPG - 1) {
                atomicExch(&g_cnt[g], 0u);
                __threadfence();
                g_sense[g] = ls;
            } else {
                while (g_sense[g] != ls) { }
            }
            __threadfence();
        }
        local_sense ^= 1;
        __syncthreads();
    }

    // ---- final projection p = h_final @ Wph + bp ; h_final in g_hbuf[0] ----
    if (jc == 0) {
        for (int o = tid; o < RPG * NCLS; o += NTHR) {
            int r = o / NCLS, c = o % NCLS;
            const float4* hrow = (const float4*)(g_hbuf[0] + (row0 + r) * HID);
            float a0 = 0.f, a1 = 0.f, a2 = 0.f, a3 = 0.f;
            #pragma unroll 4
            for (int kq = 0; kq < HID / 4; ++kq) {
                float4 hv = __ldcg(hrow + kq);
                a0 += hv.x * __ldg(Wph + (4 * kq + 0) * NCLS + c);
                a1 += hv.y * __ldg(Wph + (4 * kq + 1) * NCLS + c);
                a2 += hv.z * __ldg(Wph + (4 * kq + 2) * NCLS + c);
                a3 += hv.w * __ldg(Wph + (4 * kq + 3) * NCLS + c);
            }
            out[(row0 + r) * NCLS + c] = (a0 + a1) + (a2 + a3) + __ldg(bp + c);
        }
    }
}

extern "C" void kernel_launch(void* const* d_in, const int* in_sizes, int n_in,
                              void* d_out, int out_size) {
    const float* x   = (const float*)d_in[0];
    const float* Whx = (const float*)d_in[1];
    const float* Whh = (const float*)d_in[2];
    const float* Wph = (const float*)d_in[3];
    const float* bh  = (const float*)d_in[4];
    const float* bp  = (const float*)d_in[5];

    const size_t smem_bytes = (size_t)RPG * KTOT * sizeof(float);   // 36864 B
    rnn_regw2<<<GROUPS * CPG, NTHR, smem_bytes>>>(
        x, Whx, Whh, Wph, bh, bp, (float*)d_out);
}